// round 16
// baseline (speedup 1.0000x reference)
#include <cuda_runtime.h>
#include <math.h>

#define N_TOKENS  2048
#define D_IN      1024
#define D_HID     4096
#define D_OUT     1024
#define N_EXPERTS 8
#define TOPK      2
#define N_ASSIGN  (N_TOKENS * TOPK)   // 4096

// ---------------- device scratch (static globals: no allocation APIs) --------
__device__ int   g_cnt[N_EXPERTS];
__device__ int   g_cur[N_EXPERTS];
__device__ int   g_off[N_EXPERTS];
__device__ int   g_topk_idx[N_ASSIGN];
__device__ float g_topk_w[N_ASSIGN];
__device__ int   g_rowtok[N_ASSIGN];    // compacted row -> token
__device__ int   g_assign[N_ASSIGN];    // token*2+k   -> compacted row
__device__ float g_h[(size_t)N_ASSIGN * D_HID];   // 64 MB
__device__ float g_y[(size_t)N_ASSIGN * D_OUT];   // 16 MB

// ---------------- kernel 0: zero counters -----------------------------------
__global__ void moe_zero_kernel() {
    int t = threadIdx.x;
    if (t < N_EXPERTS) { g_cnt[t] = 0; g_cur[t] = 0; }
}

// ---------------- kernel 1: router (one warp per token) ---------------------
__global__ void moe_router_kernel(const float* __restrict__ x,
                                  const float* __restrict__ Wr,
                                  const float* __restrict__ br) {
    int gw   = (blockIdx.x * blockDim.x + threadIdx.x) >> 5;
    int lane = threadIdx.x & 31;
    if (gw >= N_TOKENS) return;
    const float* xr = x + (size_t)gw * D_IN;

    float acc[N_EXPERTS];
#pragma unroll
    for (int e = 0; e < N_EXPERTS; ++e) acc[e] = 0.f;

    for (int d = lane; d < D_IN; d += 32) {
        float xv = xr[d];
        float4 wa = *(const float4*)(Wr + (size_t)d * N_EXPERTS);
        float4 wb = *(const float4*)(Wr + (size_t)d * N_EXPERTS + 4);
        acc[0] = fmaf(xv, wa.x, acc[0]);
        acc[1] = fmaf(xv, wa.y, acc[1]);
        acc[2] = fmaf(xv, wa.z, acc[2]);
        acc[3] = fmaf(xv, wa.w, acc[3]);
        acc[4] = fmaf(xv, wb.x, acc[4]);
        acc[5] = fmaf(xv, wb.y, acc[5]);
        acc[6] = fmaf(xv, wb.z, acc[6]);
        acc[7] = fmaf(xv, wb.w, acc[7]);
    }
#pragma unroll
    for (int e = 0; e < N_EXPERTS; ++e) {
#pragma unroll
        for (int o = 16; o > 0; o >>= 1)
            acc[e] += __shfl_down_sync(0xffffffffu, acc[e], o);
    }

    if (lane == 0) {
        float l[N_EXPERTS];
#pragma unroll
        for (int e = 0; e < N_EXPERTS; ++e) l[e] = acc[e] + br[e];
        float m = l[0];
#pragma unroll
        for (int e = 1; e < N_EXPERTS; ++e) m = fmaxf(m, l[e]);
        float p[N_EXPERTS];
        float s = 0.f;
#pragma unroll
        for (int e = 0; e < N_EXPERTS; ++e) { p[e] = expf(l[e] - m); s += p[e]; }
        float inv = 1.0f / s;

        // stable top-2 (strict >, ascending scan == jax.lax.top_k tie-break)
        int i1 = 0;
#pragma unroll
        for (int e = 1; e < N_EXPERTS; ++e) if (p[e] > p[i1]) i1 = e;
        int i2 = -1;
#pragma unroll
        for (int e = 0; e < N_EXPERTS; ++e) {
            if (e == i1) continue;
            if (i2 < 0 || p[e] > p[i2]) i2 = e;
        }

        g_topk_idx[gw * 2 + 0] = i1;
        g_topk_idx[gw * 2 + 1] = i2;
        g_topk_w[gw * 2 + 0]   = p[i1] * inv;
        g_topk_w[gw * 2 + 1]   = p[i2] * inv;
        atomicAdd(&g_cnt[i1], 1);
        atomicAdd(&g_cnt[i2], 1);
    }
}

// ---------------- kernel 2: exclusive scan over 8 experts -------------------
__global__ void moe_scan_kernel() {
    if (threadIdx.x == 0 && blockIdx.x == 0) {
        int o = 0;
        for (int e = 0; e < N_EXPERTS; ++e) { g_off[e] = o; o += g_cnt[e]; }
    }
}

// ---------------- kernel 3: place assignments into compacted rows -----------
__global__ void moe_place_kernel() {
    int n = blockIdx.x * blockDim.x + threadIdx.x;
    if (n >= N_TOKENS) return;
#pragma unroll
    for (int k = 0; k < TOPK; ++k) {
        int e   = g_topk_idx[n * 2 + k];
        int pos = atomicAdd(&g_cur[e], 1);
        int row = g_off[e] + pos;
        g_rowtok[row]       = n;
        g_assign[n * 2 + k] = row;
    }
}

// ---------------- grouped GEMM -----------------------------------------------
// PHASE 1: C(g_h) = relu( gather(x) @ W1[e] + b1[e] )   K=1024, N=4096
// PHASE 2: C(g_y) =        g_h      @ W2[e] + b2[e]     K=4096, N=1024
#define BM 128
#define BN 128
#define BK 16
#define AS_LD 132

template <int PHASE>
__global__ __launch_bounds__(256, 2) void moe_gemm_kernel(
    const float* __restrict__ Aext,      // x for phase 1, unused for phase 2
    const float* __restrict__ Bbase,     // W1 or W2 (E stacked, row-major KxN)
    const float* __restrict__ biasbase,  // b1 or b2 (E stacked)
    int K, int N, int lda)
{
    constexpr bool GATHER = (PHASE == 1);
    constexpr bool RELU   = (PHASE == 1);

    const int e   = blockIdx.z;
    const int cnt = g_cnt[e];
    const int m0  = blockIdx.y * BM;
    if (m0 >= cnt) return;
    const int off = g_off[e];
    const int n0  = blockIdx.x * BN;

    const float* A    = GATHER ? Aext : g_h;
    float*       C    = RELU ? g_h : g_y;
    const int    ldc  = N;
    const float* B    = Bbase + (size_t)e * K * N + n0;
    const float* bias = biasbase + (size_t)e * N + n0;

    __shared__ __align__(16) float As[BK][AS_LD];
    __shared__ __align__(16) float Bs[BK][BN];

    const int tid = threadIdx.x;

    // A-tile loader mapping: 128 rows x 16 k = 512 float4, 2 per thread
    const int arow0 = tid >> 2;               // 0..63
    const int arow1 = arow0 + 64;             // 64..127
    const int ak    = (tid & 3) << 2;         // 0,4,8,12
    const bool v0 = (m0 + arow0) < cnt;
    const bool v1 = (m0 + arow1) < cnt;
    int r0 = off + m0 + arow0;
    int r1 = off + m0 + arow1;
    int s0 = GATHER ? (v0 ? g_rowtok[r0] : 0) : (v0 ? r0 : 0);
    int s1 = GATHER ? (v1 ? g_rowtok[r1] : 0) : (v1 ? r1 : 0);
    const float* Aptr0 = A + (size_t)s0 * lda + ak;
    const float* Aptr1 = A + (size_t)s1 * lda + ak;

    // B-tile loader mapping: 16 k x 128 n = 512 float4, 2 per thread
    const int brow = tid >> 5;                // 0..7 (and +8)
    const int bcol = (tid & 31) << 2;         // 0..124

    // compute mapping: 16x16 threads, 8x8 microtile
    const int ty = tid >> 4, tx = tid & 15;
    const int mr = ty << 3, nc = tx << 3;

    float acc[8][8];
#pragma unroll
    for (int i = 0; i < 8; ++i)
#pragma unroll
        for (int j = 0; j < 8; ++j) acc[i][j] = 0.f;

    const float4 z4 = make_float4(0.f, 0.f, 0.f, 0.f);
    float4 pa0 = v0 ? *(const float4*)(Aptr0) : z4;
    float4 pa1 = v1 ? *(const float4*)(Aptr1) : z4;
    float4 pb0 = *(const float4*)(B + (size_t)brow * N + bcol);
    float4 pb1 = *(const float4*)(B + (size_t)(brow + 8) * N + bcol);

    for (int k0 = 0; k0 < K; k0 += BK) {
        As[ak + 0][arow0] = pa0.x;
        As[ak + 1][arow0] = pa0.y;
        As[ak + 2][arow0] = pa0.z;
        As[ak + 3][arow0] = pa0.w;
        As[ak + 0][arow1] = pa1.x;
        As[ak + 1][arow1] = pa1.y;
        As[ak + 2][arow1] = pa1.z;
        As[ak + 3][arow1] = pa1.w;
        *(float4*)&Bs[brow][bcol]     = pb0;
        *(float4*)&Bs[brow + 8][bcol] = pb1;
        __syncthreads();

        int kn = k0 + BK;
        if (kn < K) {   // register prefetch of next tile
            pa0 = v0 ? *(const float4*)(Aptr0 + kn) : z4;
            pa1 = v1 ? *(const float4*)(Aptr1 + kn) : z4;
            pb0 = *(const float4*)(B + (size_t)(kn + brow) * N + bcol);
            pb1 = *(const float4*)(B + (size_t)(kn + brow + 8) * N + bcol);
        }

#pragma unroll
        for (int kk = 0; kk < BK; ++kk) {
            float4 a0 = *(const float4*)&As[kk][mr];
            float4 a1 = *(const float4*)&As[kk][mr + 4];
            float4 b0 = *(const float4*)&Bs[kk][nc];
            float4 b1 = *(const float4*)&Bs[kk][nc + 4];
            float av[8] = {a0.x, a0.y, a0.z, a0.w, a1.x, a1.y, a1.z, a1.w};
            float bv[8] = {b0.x, b0.y, b0.z, b0.w, b1.x, b1.y, b1.z, b1.w};
#pragma unroll
            for (int i = 0; i < 8; ++i)
#pragma unroll
                for (int j = 0; j < 8; ++j)
                    acc[i][j] = fmaf(av[i], bv[j], acc[i][j]);
        }
        __syncthreads();
    }

    // epilogue: bias (+relu), vectorized stores
#pragma unroll
    for (int i = 0; i < 8; ++i) {
        int m = m0 + mr + i;
        if (m < cnt) {
            float* Crow = C + (size_t)(off + m) * ldc + n0 + nc;
            float4 o0, o1;
            o0.x = acc[i][0] + bias[nc + 0];
            o0.y = acc[i][1] + bias[nc + 1];
            o0.z = acc[i][2] + bias[nc + 2];
            o0.w = acc[i][3] + bias[nc + 3];
            o1.x = acc[i][4] + bias[nc + 4];
            o1.y = acc[i][5] + bias[nc + 5];
            o1.z = acc[i][6] + bias[nc + 6];
            o1.w = acc[i][7] + bias[nc + 7];
            if (RELU) {
                o0.x = fmaxf(o0.x, 0.f); o0.y = fmaxf(o0.y, 0.f);
                o0.z = fmaxf(o0.z, 0.f); o0.w = fmaxf(o0.w, 0.f);
                o1.x = fmaxf(o1.x, 0.f); o1.y = fmaxf(o1.y, 0.f);
                o1.z = fmaxf(o1.z, 0.f); o1.w = fmaxf(o1.w, 0.f);
            }
            *(float4*)(Crow + 0) = o0;
            *(float4*)(Crow + 4) = o1;
        }
    }
}

// ---------------- kernel 6: weighted combine --------------------------------
__global__ void moe_combine_kernel(float* __restrict__ out) {
    int idx = blockIdx.x * blockDim.x + threadIdx.x;     // over N_TOKENS * D_OUT/4
    if (idx >= N_TOKENS * (D_OUT / 4)) return;
    int n  = idx >> 8;        // D_OUT/4 == 256
    int d4 = idx & 255;
    int   a0 = g_assign[n * 2 + 0];
    int   a1 = g_assign[n * 2 + 1];
    float w0 = g_topk_w[n * 2 + 0];
    float w1 = g_topk_w[n * 2 + 1];
    float4 y0 = ((const float4*)(g_y + (size_t)a0 * D_OUT))[d4];
    float4 y1 = ((const float4*)(g_y + (size_t)a1 * D_OUT))[d4];
    float4 o;
    o.x = fmaf(w0, y0.x, w1 * y1.x);
    o.y = fmaf(w0, y0.y, w1 * y1.y);
    o.z = fmaf(w0, y0.z, w1 * y1.z);
    o.w = fmaf(w0, y0.w, w1 * y1.w);
    ((float4*)out)[idx] = o;
}

// ---------------- launch ------------------------------------------------------
extern "C" void kernel_launch(void* const* d_in, const int* in_sizes, int n_in,
                              void* d_out, int out_size) {
    const float* x  = (const float*)d_in[0];
    const float* Wr = (const float*)d_in[1];
    const float* br = (const float*)d_in[2];
    const float* W1 = (const float*)d_in[3];
    const float* b1 = (const float*)d_in[4];
    const float* W2 = (const float*)d_in[5];
    const float* b2 = (const float*)d_in[6];
    float* out = (float*)d_out;

    moe_zero_kernel<<<1, 32>>>();
    moe_router_kernel<<<N_TOKENS / 8, 256>>>(x, Wr, br);   // 8 warps/block
    moe_scan_kernel<<<1, 32>>>();
    moe_place_kernel<<<N_TOKENS / 256, 256>>>();

    {   // phase 1: h = relu(gather(x) @ W1[e] + b1[e])   M<=2048, K=1024, N=4096
        dim3 grid(D_HID / BN, (N_TOKENS + BM - 1) / BM, N_EXPERTS);
        moe_gemm_kernel<1><<<grid, 256>>>(x, W1, b1, D_IN, D_HID, D_IN);
    }
    {   // phase 2: y = h @ W2[e] + b2[e]                 K=4096, N=1024
        dim3 grid(D_OUT / BN, (N_TOKENS + BM - 1) / BM, N_EXPERTS);
        moe_gemm_kernel<2><<<grid, 256>>>(nullptr, W2, b2, D_HID, D_OUT, D_HID);
    }

    moe_combine_kernel<<<(N_TOKENS * (D_OUT / 4)) / 256, 256>>>(out);
}